// round 7
// baseline (speedup 1.0000x reference)
#include <cuda_runtime.h>
#include <cuda_bf16.h>

// Shapes (fixed per reference)
#define B_SZ     8192
#define K_SZ     50
#define KG_DIM   64
#define IN_SZ    512
#define CC       64
#define OUT_SZ   1024

// ---------------------------------------------------------------------------
// Packed fp32x2 helpers (sm_103a FFMA2 path -- bit-exact IEEE fp32 per lane)
// ---------------------------------------------------------------------------
__device__ __forceinline__ void ffma2(unsigned long long& d,
                                      unsigned long long a,
                                      unsigned long long b) {
    asm("fma.rn.f32x2 %0, %1, %2, %0;" : "+l"(d) : "l"(a), "l"(b));
}
__device__ __forceinline__ unsigned long long fadd2(unsigned long long a,
                                                    unsigned long long b) {
    unsigned long long r;
    asm("add.rn.f32x2 %0, %1, %2;" : "=l"(r) : "l"(a), "l"(b));
    return r;
}
__device__ __forceinline__ void unpack2(unsigned long long v, float& lo, float& hi) {
    asm("mov.b64 {%0, %1}, %2;" : "=f"(lo), "=f"(hi) : "l"(v));
}

// ---------------------------------------------------------------------------
// Scratch (static device globals -- no runtime allocation allowed)
// ---------------------------------------------------------------------------
__device__ float g_h1[B_SZ * 128];
__device__ float g_h2[B_SZ * 512];
__device__ float g_h3[B_SZ * 128];
__device__ float g_h4[B_SZ * CC];
__device__ float g_know[B_SZ * CC];
__device__ int   g_cnt[B_SZ];
__device__ int   g_cidx[B_SZ * K_SZ];

// ---------------------------------------------------------------------------
// Kernel 1: warp-per-row compaction of masked gather indices.
// ---------------------------------------------------------------------------
__global__ void __launch_bounds__(256) compact_kernel(
    const int* __restrict__ idx, const int* __restrict__ mask,
    int* __restrict__ cidx, int* __restrict__ cnt)
{
    int b = blockIdx.x * (blockDim.x >> 5) + (threadIdx.x >> 5);
    if (b >= B_SZ) return;
    int l = threadIdx.x & 31;
    int base = b * K_SZ;
    int c = 0;
    #pragma unroll
    for (int k0 = 0; k0 < K_SZ; k0 += 32) {
        int k = k0 + l;
        bool m = (k < K_SZ) && (mask[base + k] != 0);
        unsigned bal = __ballot_sync(0xffffffffu, m);
        int pos = c + __popc(bal & ((1u << l) - 1u));
        if (m) cidx[base + pos] = idx[base + k];
        c += __popc(bal);
    }
    if (l == 0) cnt[b] = c;
}

// ---------------------------------------------------------------------------
// Kernel 2: knowledge branch (v3 -- packed f32x2, one warp per batch).
//   knowledge[b][c] = sum_j relu( kg[cidx[b][j]] . Wkg[:,c] + bkg[c] )
// Each lane owns the column PAIR (2l, 2l+1); Wkg column-pairs live in 64 u64
// registers (columns are contiguous -> direct u64 loads). The gathered kg row
// is staged in smem pre-duplicated ((g,g) pairs) so the inner loop is one
// broadcast LDS.128 per two d-steps + FFMA2. Double-buffered row prefetch,
// 4 rotating packed accumulators, direct stores.
// ---------------------------------------------------------------------------
__global__ void __launch_bounds__(256) knowledge_kernel(
    const float* __restrict__ kg, const float* __restrict__ Wkg,
    const float* __restrict__ bkg, const int* __restrict__ cidx,
    const int* __restrict__ cnt, float* __restrict__ know)
{
    __shared__ __align__(16) float sg[8][2][2 * KG_DIM];  // duplicated rows, dbl-buffered

    int tid = threadIdx.x;
    int w   = tid >> 5;
    int l   = tid & 31;
    int b   = blockIdx.x * 8 + w;

    // Wkg column pair (2l, 2l+1) for every d, packed
    unsigned long long Wr[KG_DIM];
    #pragma unroll
    for (int d = 0; d < KG_DIM; d++)
        Wr[d] = *(const unsigned long long*)&Wkg[d * CC + 2 * l];
    unsigned long long bc2 = *(const unsigned long long*)&bkg[2 * l];

    int n = cnt[b];
    const int* cp = cidx + b * K_SZ;
    float acc0 = 0.f, acc1 = 0.f;

    if (n > 0) {
        float2 g2 = *(const float2*)(kg + (long)cp[0] * KG_DIM + 2 * l);
        *(float4*)&sg[w][0][4 * l] = make_float4(g2.x, g2.x, g2.y, g2.y);
    }
    __syncwarp();

    for (int j = 0; j < n; j++) {
        int buf = j & 1;
        float2 nx;
        bool more = (j + 1 < n);
        if (more)
            nx = *(const float2*)(kg + (long)cp[j + 1] * KG_DIM + 2 * l);

        unsigned long long s0 = bc2, s1 = 0ull, s2 = 0ull, s3 = 0ull;
        #pragma unroll
        for (int d = 0; d < KG_DIM; d += 4) {
            ulonglong2 ga = *(const ulonglong2*)&sg[w][buf][2 * d];      // (g[d],g[d]),(g[d+1],g[d+1])
            ulonglong2 gb = *(const ulonglong2*)&sg[w][buf][2 * d + 4];  // (g[d+2],..),(g[d+3],..)
            ffma2(s0, ga.x, Wr[d + 0]);
            ffma2(s1, ga.y, Wr[d + 1]);
            ffma2(s2, gb.x, Wr[d + 2]);
            ffma2(s3, gb.y, Wr[d + 3]);
        }
        unsigned long long t = fadd2(fadd2(s0, s1), fadd2(s2, s3));
        float v0, v1;
        unpack2(t, v0, v1);
        acc0 += fmaxf(v0, 0.f);
        acc1 += fmaxf(v1, 0.f);

        if (more)
            *(float4*)&sg[w][buf ^ 1][4 * l] = make_float4(nx.x, nx.x, nx.y, nx.y);
        __syncwarp();
    }
    *(float2*)&know[(long)b * CC + 2 * l] = make_float2(acc0, acc1);
}

// ---------------------------------------------------------------------------
// Kernel 3: double-buffered tiled SGEMM with packed-f32x2 inner loop.
// C = act(A @ W + bias) [+ addk].  A:[M,K], W:[K,N], C:[M,N], BN=64, 256 thr.
// B tile stored PRE-DUPLICATED in smem ((b,b) pairs); accumulators packed
// over m-pairs, so A-pairs come straight from LDS.128 of transposed As.
// Per k-step (TM=8): 4 LDS.128 + 16 FFMA2 (32 lane-FMA).
// Per-element accumulation order identical to the scalar version -> bit-exact.
// ---------------------------------------------------------------------------
template <int BM_, int BK_, int TM_, bool RELU, bool ADDK>
__global__ void __launch_bounds__(256) gemm_kernel(
    const float* __restrict__ A, const float* __restrict__ W,
    const float* __restrict__ bias, const float* __restrict__ addk,
    float* __restrict__ C, int M, int N, int K)
{
    constexpr int BN_  = 64;
    constexpr int ALD  = BM_ + 4;               // padded transposed-A stride (16B-aligned rows)
    constexpr int A_PT = (BM_ * BK_ / 4) / 256; // float4 per thread (A tile)
    constexpr int B_PT = (BK_ * BN_ / 4) / 256; // float4 per thread (B tile)
    constexpr int ACOLS4 = BK_ / 4;
    constexpr int TP   = TM_ / 2;               // m-pairs per thread

    __shared__ __align__(16) float As [2][BK_ * ALD];      // transposed: As[k][m]
    __shared__ __align__(16) float Bsd[2][BK_ * 2 * BN_];  // duplicated: (b,b) pairs

    int tid = threadIdx.x;
    int m0 = blockIdx.y * BM_;
    int n0 = blockIdx.x * BN_;

    // load mappings
    int a_row[A_PT], a_col[A_PT];
    const float* Ap[A_PT];
    #pragma unroll
    for (int t = 0; t < A_PT; t++) {
        int id = tid + t * 256;
        a_row[t] = id / ACOLS4;
        a_col[t] = (id % ACOLS4) * 4;
        Ap[t] = A + (long)(m0 + a_row[t]) * K + a_col[t];
    }
    int b_row[B_PT], b_col[B_PT];
    const float* Bp[B_PT];
    #pragma unroll
    for (int t = 0; t < B_PT; t++) {
        int id = tid + t * 256;
        b_row[t] = id >> 4;
        b_col[t] = (id & 15) * 4;
        Bp[t] = W + (long)b_row[t] * N + n0 + b_col[t];
    }

    // compute mapping: 16(ty, m) x 16(tx, n)
    int ty = tid >> 4, tx = tid & 15;
    int mb = ty * TM_, nb = tx * 4;

    unsigned long long acc2[TP][4];
    #pragma unroll
    for (int p = 0; p < TP; p++)
        #pragma unroll
        for (int j = 0; j < 4; j++) acc2[p][j] = 0ull;

    float4 pa[A_PT], pb[B_PT];

    // preload tile 0
    #pragma unroll
    for (int t = 0; t < A_PT; t++) { pa[t] = *(const float4*)Ap[t]; Ap[t] += BK_; }
    #pragma unroll
    for (int t = 0; t < B_PT; t++) { pb[t] = *(const float4*)Bp[t]; Bp[t] += (long)BK_ * N; }
    #pragma unroll
    for (int t = 0; t < A_PT; t++) {
        As[0][(a_col[t] + 0) * ALD + a_row[t]] = pa[t].x;
        As[0][(a_col[t] + 1) * ALD + a_row[t]] = pa[t].y;
        As[0][(a_col[t] + 2) * ALD + a_row[t]] = pa[t].z;
        As[0][(a_col[t] + 3) * ALD + a_row[t]] = pa[t].w;
    }
    #pragma unroll
    for (int t = 0; t < B_PT; t++) {
        float4 bv = pb[t];
        *(float4*)&Bsd[0][b_row[t] * 2 * BN_ + 2 * b_col[t]]     = make_float4(bv.x, bv.x, bv.y, bv.y);
        *(float4*)&Bsd[0][b_row[t] * 2 * BN_ + 2 * b_col[t] + 4] = make_float4(bv.z, bv.z, bv.w, bv.w);
    }
    __syncthreads();

    int nt = K / BK_;
    for (int kt = 0; kt < nt; kt++) {
        int cur = kt & 1;
        bool more = (kt + 1 < nt);
        if (more) {
            #pragma unroll
            for (int t = 0; t < A_PT; t++) { pa[t] = *(const float4*)Ap[t]; Ap[t] += BK_; }
            #pragma unroll
            for (int t = 0; t < B_PT; t++) { pb[t] = *(const float4*)Bp[t]; Bp[t] += (long)BK_ * N; }
        }

        const float* Asc = As[cur];
        const float* Bsc = Bsd[cur];
        #pragma unroll
        for (int k = 0; k < BK_; k++) {
            ulonglong2 ap[TP / 2 + 1];  // a m-pairs
            unsigned long long av[TP];
            #pragma unroll
            for (int i = 0; i < TP; i += 2) {
                ulonglong2 t2 = *(const ulonglong2*)&Asc[k * ALD + mb + 2 * i];
                av[i] = t2.x; av[i + 1] = t2.y;
            }
            ulonglong2 b01 = *(const ulonglong2*)&Bsc[k * 2 * BN_ + 2 * nb];      // (n0,n0),(n1,n1)
            ulonglong2 b23 = *(const ulonglong2*)&Bsc[k * 2 * BN_ + 2 * nb + 4];  // (n2,n2),(n3,n3)
            #pragma unroll
            for (int p = 0; p < TP; p++) {
                ffma2(acc2[p][0], av[p], b01.x);
                ffma2(acc2[p][1], av[p], b01.y);
                ffma2(acc2[p][2], av[p], b23.x);
                ffma2(acc2[p][3], av[p], b23.y);
            }
        }

        if (more) {
            int nxt = cur ^ 1;
            #pragma unroll
            for (int t = 0; t < A_PT; t++) {
                As[nxt][(a_col[t] + 0) * ALD + a_row[t]] = pa[t].x;
                As[nxt][(a_col[t] + 1) * ALD + a_row[t]] = pa[t].y;
                As[nxt][(a_col[t] + 2) * ALD + a_row[t]] = pa[t].z;
                As[nxt][(a_col[t] + 3) * ALD + a_row[t]] = pa[t].w;
            }
            #pragma unroll
            for (int t = 0; t < B_PT; t++) {
                float4 bv = pb[t];
                *(float4*)&Bsd[nxt][b_row[t] * 2 * BN_ + 2 * b_col[t]]     = make_float4(bv.x, bv.x, bv.y, bv.y);
                *(float4*)&Bsd[nxt][b_row[t] * 2 * BN_ + 2 * b_col[t] + 4] = make_float4(bv.z, bv.z, bv.w, bv.w);
            }
            __syncthreads();
        }
    }

    // unpack packed accumulators -> scalar epilogue (unchanged semantics)
    float acc[TM_][4];
    #pragma unroll
    for (int p = 0; p < TP; p++)
        #pragma unroll
        for (int j = 0; j < 4; j++)
            unpack2(acc2[p][j], acc[2 * p][j], acc[2 * p + 1][j]);

    float bias4[4];
    *(float4*)&bias4[0] = *(const float4*)&bias[n0 + nb];

    #pragma unroll
    for (int i = 0; i < TM_; i++) {
        int m = m0 + mb + i;
        float v[4];
        #pragma unroll
        for (int j = 0; j < 4; j++) {
            float t = acc[i][j] + bias4[j];
            if (RELU) t = fmaxf(t, 0.f);
            v[j] = t;
        }
        if (ADDK) {
            float kv[4];
            *(float4*)&kv[0] = *(const float4*)&addk[(long)m * N + n0 + nb];
            #pragma unroll
            for (int j = 0; j < 4; j++) v[j] += kv[j];
        }
        *(float4*)&C[(long)m * N + n0 + nb] = *(float4*)&v[0];
    }
}

// ---------------------------------------------------------------------------
// Launcher
// Input order (metadata): x, kg, idx, mask, Wkg, bkg, W1a,b1a, W1b,b1b,
//                         W1c,b1c, W1d,b1d, W2,b2.  Output: float [8192,1024].
// ---------------------------------------------------------------------------
extern "C" void kernel_launch(void* const* d_in, const int* in_sizes, int n_in,
                              void* d_out, int out_size)
{
    const float* x    = (const float*)d_in[0];
    const float* kg   = (const float*)d_in[1];
    const int*   idx  = (const int*)  d_in[2];
    const int*   mask = (const int*)  d_in[3];
    const float* Wkg  = (const float*)d_in[4];
    const float* bkg  = (const float*)d_in[5];
    const float* W1a  = (const float*)d_in[6];
    const float* b1a  = (const float*)d_in[7];
    const float* W1b  = (const float*)d_in[8];
    const float* b1b  = (const float*)d_in[9];
    const float* W1c  = (const float*)d_in[10];
    const float* b1c  = (const float*)d_in[11];
    const float* W1d  = (const float*)d_in[12];
    const float* b1d  = (const float*)d_in[13];
    const float* W2   = (const float*)d_in[14];
    const float* b2   = (const float*)d_in[15];
    float* out = (float*)d_out;

    float *h1, *h2, *h3, *h4, *know;
    int *cnt, *cidx;
    cudaGetSymbolAddress((void**)&h1,   g_h1);
    cudaGetSymbolAddress((void**)&h2,   g_h2);
    cudaGetSymbolAddress((void**)&h3,   g_h3);
    cudaGetSymbolAddress((void**)&h4,   g_h4);
    cudaGetSymbolAddress((void**)&know, g_know);
    cudaGetSymbolAddress((void**)&cnt,  g_cnt);
    cudaGetSymbolAddress((void**)&cidx, g_cidx);

    // knowledge branch
    compact_kernel<<<B_SZ / 8, 256>>>(idx, mask, cidx, cnt);
    knowledge_kernel<<<B_SZ / 8, 256>>>(kg, Wkg, bkg, cidx, cnt, know);

    // dense MLP chain
    // L1a: [8192,512] @ [512,128]
    gemm_kernel<64, 32, 4, true, false><<<dim3(128 / 64, B_SZ / 64), 256>>>(
        x,  W1a, b1a, nullptr, h1, B_SZ, 128, IN_SZ);
    // L1b: [8192,128] @ [128,512]
    gemm_kernel<128, 16, 8, true, false><<<dim3(512 / 64, B_SZ / 128), 256>>>(
        h1, W1b, b1b, nullptr, h2, B_SZ, 512, 128);
    // L1c: [8192,512] @ [512,128]
    gemm_kernel<64, 32, 4, true, false><<<dim3(128 / 64, B_SZ / 64), 256>>>(
        h2, W1c, b1c, nullptr, h3, B_SZ, 128, 512);
    // L1d: [8192,128] @ [128,64] + knowledge (fused add)
    gemm_kernel<64, 32, 4, true, true><<<dim3(CC / 64, B_SZ / 64), 256>>>(
        h3, W1d, b1d, know, h4, B_SZ, CC, 128);
    // L2:  [8192,64] @ [64,1024]
    gemm_kernel<128, 16, 8, false, false><<<dim3(OUT_SZ / 64, B_SZ / 128), 256>>>(
        h4, W2, b2, nullptr, out, B_SZ, OUT_SZ, CC);
}

// round 8
// speedup vs baseline: 1.7710x; 1.7710x over previous
#include <cuda_runtime.h>
#include <cuda_bf16.h>
#include <cstdint>

// Shapes (fixed per reference)
#define B_SZ     8192
#define K_SZ     50
#define KG_DIM   64
#define IN_SZ    512
#define CC       64
#define OUT_SZ   1024

// ---------------------------------------------------------------------------
// Scratch (static device globals -- no runtime allocation allowed)
// ---------------------------------------------------------------------------
__device__ float g_h1[B_SZ * 128];
__device__ float g_h2[B_SZ * 512];
__device__ float g_h3[B_SZ * 128];
__device__ float g_h4[B_SZ * CC];
__device__ float g_know[B_SZ * CC];
__device__ int   g_cnt[B_SZ];
__device__ int   g_cidx[B_SZ * K_SZ];

// ---------------------------------------------------------------------------
// tf32 helpers
// ---------------------------------------------------------------------------
__device__ __forceinline__ float to_tf32(float x) {
    uint32_t u;
    asm("cvt.rna.tf32.f32 %0, %1;" : "=r"(u) : "f"(x));
    return __uint_as_float(u);
}
__device__ __forceinline__ void mma_tf32(float* d, const uint32_t* a, const uint32_t* b) {
    asm volatile(
        "mma.sync.aligned.m16n8k8.row.col.f32.tf32.tf32.f32 "
        "{%0,%1,%2,%3}, {%4,%5,%6,%7}, {%8,%9}, {%0,%1,%2,%3};"
        : "+f"(d[0]), "+f"(d[1]), "+f"(d[2]), "+f"(d[3])
        : "r"(a[0]), "r"(a[1]), "r"(a[2]), "r"(a[3]), "r"(b[0]), "r"(b[1]));
}

// ---------------------------------------------------------------------------
// Kernel 1: warp-per-row compaction of masked gather indices.
// ---------------------------------------------------------------------------
__global__ void __launch_bounds__(256) compact_kernel(
    const int* __restrict__ idx, const int* __restrict__ mask,
    int* __restrict__ cidx, int* __restrict__ cnt)
{
    int b = blockIdx.x * (blockDim.x >> 5) + (threadIdx.x >> 5);
    if (b >= B_SZ) return;
    int l = threadIdx.x & 31;
    int base = b * K_SZ;
    int c = 0;
    #pragma unroll
    for (int k0 = 0; k0 < K_SZ; k0 += 32) {
        int k = k0 + l;
        bool m = (k < K_SZ) && (mask[base + k] != 0);
        unsigned bal = __ballot_sync(0xffffffffu, m);
        int pos = c + __popc(bal & ((1u << l) - 1u));
        if (m) cidx[base + pos] = idx[base + k];
        c += __popc(bal);
    }
    if (l == 0) cnt[b] = c;
}

// ---------------------------------------------------------------------------
// Kernel 2: knowledge branch (Round-6 proven version; exact fp32).
//   knowledge[b][c] = sum_j relu( kg[cidx[b][j]] . Wkg[:,c] + bkg[c] )
// 8 warps = 4 warp-pairs; pair owns KB_PW batches; lane owns one column with
// its Wkg column in registers; gathered row double-buffered in smem.
// ---------------------------------------------------------------------------
#define KB_PW 4
__global__ void __launch_bounds__(256) knowledge_kernel(
    const float* __restrict__ kg, const float* __restrict__ Wkg,
    const float* __restrict__ bkg, const int* __restrict__ cidx,
    const int* __restrict__ cnt, float* __restrict__ know)
{
    __shared__ float sg[8][2][KG_DIM];

    int tid = threadIdx.x;
    int w   = tid >> 5;
    int l   = tid & 31;
    int pr  = w >> 1;
    int hf  = w & 1;
    int c   = hf * 32 + l;

    float Wr[KG_DIM];
    #pragma unroll
    for (int d = 0; d < KG_DIM; d++) Wr[d] = Wkg[d * CC + c];
    float bc = bkg[c];

    for (int bi = 0; bi < KB_PW; bi++) {
        int b = (blockIdx.x * 4 + pr) * KB_PW + bi;
        int n = cnt[b];
        const int* cp = cidx + b * K_SZ;
        float acc = 0.f;

        if (n > 0) {
            int r = cp[0];
            float2 g2 = *(const float2*)(kg + (long)r * KG_DIM + 2 * l);
            *(float2*)&sg[w][0][2 * l] = g2;
        }
        __syncwarp();

        for (int j = 0; j < n; j++) {
            int buf = j & 1;
            float2 nx;
            bool more = (j + 1 < n);
            if (more) {
                int r2 = cp[j + 1];
                nx = *(const float2*)(kg + (long)r2 * KG_DIM + 2 * l);
            }
            float s0 = bc, s1 = 0.f, s2 = 0.f, s3 = 0.f;
            #pragma unroll
            for (int d = 0; d < KG_DIM; d += 4) {
                float4 g4 = *(const float4*)&sg[w][buf][d];
                s0 = fmaf(g4.x, Wr[d + 0], s0);
                s1 = fmaf(g4.y, Wr[d + 1], s1);
                s2 = fmaf(g4.z, Wr[d + 2], s2);
                s3 = fmaf(g4.w, Wr[d + 3], s3);
            }
            float s = (s0 + s1) + (s2 + s3);
            acc += fmaxf(s, 0.f);
            if (more) *(float2*)&sg[w][buf ^ 1][2 * l] = nx;
            __syncwarp();
        }
        know[(long)b * CC + c] = acc;
    }
}

// ---------------------------------------------------------------------------
// Kernel 3: tf32 tensor-core GEMM  C = act(A @ W + bias) [+ addk]
// A:[M,K] row-major, W:[K,N] row-major, C:[M,N]. 256 threads = 8 warps
// arranged 4(m) x 2(n). BN=64, BK=16.
//   BM=128: warp tile 32x32 (2 m16-tiles); BM=64: warp tile 16x32 (1 m16-tile)
// mma.m16n8k8 tf32: per k8-step each warp loads A frags (4 LDS.32 per m-tile)
// and B frags (2 LDS.32 per n8-tile) from padded smem, 4 n8-tiles.
// Inputs rounded to tf32 (cvt.rna) at the smem-staging store; fp32 accum;
// exact-fp32 epilogue. Double-buffered smem with register prefetch.
// All shapes are exact tile multiples -> no bounds checks.
// ---------------------------------------------------------------------------
template <int BM_, bool RELU, bool ADDK>
__global__ void __launch_bounds__(256) tgemm_kernel(
    const float* __restrict__ A, const float* __restrict__ W,
    const float* __restrict__ bias, const float* __restrict__ addk,
    float* __restrict__ C, int M, int N, int K)
{
    constexpr int BN_ = 64;
    constexpr int BK_ = 16;
    constexpr int ALD = BK_ + 4;   // 20 floats/row (80B, 16B-aligned, conflict-free frags)
    constexpr int BLD = BN_ + 4;   // 68 floats/row (272B, 16B-aligned)
    constexpr int MT  = BM_ / 64;  // m16-tiles per warp (2 or 1)
    constexpr int A_PT = (BM_ * BK_ / 4) / 256;  // float4/thread for A tile (2 or 1)

    __shared__ float As[2][BM_ * ALD];   // As[m][k]
    __shared__ float Bs[2][BK_ * BLD];   // Bs[k][n]

    int tid = threadIdx.x;
    int m0 = blockIdx.y * BM_;
    int n0 = blockIdx.x * BN_;

    // global->smem load mappings
    int a_row[A_PT], a_col[A_PT];
    const float* Ap[A_PT];
    #pragma unroll
    for (int t = 0; t < A_PT; t++) {
        int id = tid + t * 256;
        a_row[t] = id >> 2;              // /(BK_/4)
        a_col[t] = (id & 3) * 4;
        Ap[t] = A + (long)(m0 + a_row[t]) * K + a_col[t];
    }
    int b_row = tid >> 4;                // 0..15
    int b_col = (tid & 15) * 4;          // 0..60
    const float* Bp = W + (long)b_row * N + n0 + b_col;

    // warp / fragment coordinates
    int wid = tid >> 5;
    int lane = tid & 31;
    int g  = lane >> 2;                  // groupID (0..7)
    int tg = lane & 3;                   // thread-in-group (0..3)
    int wm = wid & 3;                    // warp m index (0..3)
    int wn = wid >> 2;                   // warp n index (0..1)
    int wmb = wm * (BM_ / 4);            // warp m base (32 or 16 rows)
    int wnb = wn * 32;                   // warp n base

    float acc[MT][4][4];
    #pragma unroll
    for (int mt = 0; mt < MT; mt++)
        #pragma unroll
        for (int nt = 0; nt < 4; nt++)
            #pragma unroll
            for (int r = 0; r < 4; r++) acc[mt][nt][r] = 0.f;

    float4 pa[A_PT], pb;

    // preload chunk 0
    #pragma unroll
    for (int t = 0; t < A_PT; t++) { pa[t] = *(const float4*)Ap[t]; Ap[t] += BK_; }
    pb = *(const float4*)Bp; Bp += (long)BK_ * N;
    #pragma unroll
    for (int t = 0; t < A_PT; t++)
        *(float4*)&As[0][a_row[t] * ALD + a_col[t]] =
            make_float4(to_tf32(pa[t].x), to_tf32(pa[t].y), to_tf32(pa[t].z), to_tf32(pa[t].w));
    *(float4*)&Bs[0][b_row * BLD + b_col] =
        make_float4(to_tf32(pb.x), to_tf32(pb.y), to_tf32(pb.z), to_tf32(pb.w));
    __syncthreads();

    int nt_chunks = K / BK_;
    for (int kt = 0; kt < nt_chunks; kt++) {
        int cur = kt & 1;
        bool more = (kt + 1 < nt_chunks);
        if (more) {
            #pragma unroll
            for (int t = 0; t < A_PT; t++) { pa[t] = *(const float4*)Ap[t]; Ap[t] += BK_; }
            pb = *(const float4*)Bp; Bp += (long)BK_ * N;
        }

        const float* Asc = As[cur];
        const float* Bsc = Bs[cur];
        #pragma unroll
        for (int ks = 0; ks < BK_; ks += 8) {
            uint32_t af[MT][4];
            #pragma unroll
            for (int mt = 0; mt < MT; mt++) {
                const float* ap = &Asc[(wmb + mt * 16 + g) * ALD + ks + tg];
                af[mt][0] = __float_as_uint(ap[0]);             // (g,     k+tg)
                af[mt][1] = __float_as_uint(ap[8 * ALD]);       // (g+8,   k+tg)
                af[mt][2] = __float_as_uint(ap[4]);             // (g,     k+tg+4)
                af[mt][3] = __float_as_uint(ap[8 * ALD + 4]);   // (g+8,   k+tg+4)
            }
            uint32_t bf[4][2];
            #pragma unroll
            for (int nt = 0; nt < 4; nt++) {
                const float* bp = &Bsc[(ks + tg) * BLD + wnb + nt * 8 + g];
                bf[nt][0] = __float_as_uint(bp[0]);             // (k+tg,   n+g)
                bf[nt][1] = __float_as_uint(bp[4 * BLD]);       // (k+tg+4, n+g)
            }
            #pragma unroll
            for (int mt = 0; mt < MT; mt++)
                #pragma unroll
                for (int nt = 0; nt < 4; nt++)
                    mma_tf32(acc[mt][nt], af[mt], bf[nt]);
        }

        if (more) {
            int nxt = cur ^ 1;
            #pragma unroll
            for (int t = 0; t < A_PT; t++)
                *(float4*)&As[nxt][a_row[t] * ALD + a_col[t]] =
                    make_float4(to_tf32(pa[t].x), to_tf32(pa[t].y), to_tf32(pa[t].z), to_tf32(pa[t].w));
            *(float4*)&Bs[nxt][b_row * BLD + b_col] =
                make_float4(to_tf32(pb.x), to_tf32(pb.y), to_tf32(pb.z), to_tf32(pb.w));
            __syncthreads();
        }
    }

    // epilogue (exact fp32)
    #pragma unroll
    for (int nt = 0; nt < 4; nt++) {
        int col = n0 + wnb + nt * 8 + tg * 2;
        float2 bs2 = *(const float2*)&bias[col];
        #pragma unroll
        for (int mt = 0; mt < MT; mt++) {
            int r0 = m0 + wmb + mt * 16 + g;
            int r1 = r0 + 8;
            float v00 = acc[mt][nt][0] + bs2.x;
            float v01 = acc[mt][nt][1] + bs2.y;
            float v10 = acc[mt][nt][2] + bs2.x;
            float v11 = acc[mt][nt][3] + bs2.y;
            if (RELU) {
                v00 = fmaxf(v00, 0.f); v01 = fmaxf(v01, 0.f);
                v10 = fmaxf(v10, 0.f); v11 = fmaxf(v11, 0.f);
            }
            if (ADDK) {
                float2 k0 = *(const float2*)&addk[(long)r0 * N + col];
                float2 k1 = *(const float2*)&addk[(long)r1 * N + col];
                v00 += k0.x; v01 += k0.y; v10 += k1.x; v11 += k1.y;
            }
            *(float2*)&C[(long)r0 * N + col] = make_float2(v00, v01);
            *(float2*)&C[(long)r1 * N + col] = make_float2(v10, v11);
        }
    }
}

// ---------------------------------------------------------------------------
// Launcher
// Input order (metadata): x, kg, idx, mask, Wkg, bkg, W1a,b1a, W1b,b1b,
//                         W1c,b1c, W1d,b1d, W2,b2.  Output: float [8192,1024].
// ---------------------------------------------------------------------------
extern "C" void kernel_launch(void* const* d_in, const int* in_sizes, int n_in,
                              void* d_out, int out_size)
{
    const float* x    = (const float*)d_in[0];
    const float* kg   = (const float*)d_in[1];
    const int*   idx  = (const int*)  d_in[2];
    const int*   mask = (const int*)  d_in[3];
    const float* Wkg  = (const float*)d_in[4];
    const float* bkg  = (const float*)d_in[5];
    const float* W1a  = (const float*)d_in[6];
    const float* b1a  = (const float*)d_in[7];
    const float* W1b  = (const float*)d_in[8];
    const float* b1b  = (const float*)d_in[9];
    const float* W1c  = (const float*)d_in[10];
    const float* b1c  = (const float*)d_in[11];
    const float* W1d  = (const float*)d_in[12];
    const float* b1d  = (const float*)d_in[13];
    const float* W2   = (const float*)d_in[14];
    const float* b2   = (const float*)d_in[15];
    float* out = (float*)d_out;

    float *h1, *h2, *h3, *h4, *know;
    int *cnt, *cidx;
    cudaGetSymbolAddress((void**)&h1,   g_h1);
    cudaGetSymbolAddress((void**)&h2,   g_h2);
    cudaGetSymbolAddress((void**)&h3,   g_h3);
    cudaGetSymbolAddress((void**)&h4,   g_h4);
    cudaGetSymbolAddress((void**)&know, g_know);
    cudaGetSymbolAddress((void**)&cnt,  g_cnt);
    cudaGetSymbolAddress((void**)&cidx, g_cidx);

    // knowledge branch (exact fp32)
    compact_kernel<<<B_SZ / 8, 256>>>(idx, mask, cidx, cnt);
    knowledge_kernel<<<B_SZ / 16, 256>>>(kg, Wkg, bkg, cidx, cnt, know);

    // dense MLP chain (tf32 tensor cores, fp32 accumulate)
    // L1a: [8192,512] @ [512,128]   BM=64 -> grid 2 x 128 = 256 blocks
    tgemm_kernel<64, true, false><<<dim3(128 / 64, B_SZ / 64), 256>>>(
        x,  W1a, b1a, nullptr, h1, B_SZ, 128, IN_SZ);
    // L1b: [8192,128] @ [128,512]   BM=128 -> grid 8 x 64 = 512 blocks
    tgemm_kernel<128, true, false><<<dim3(512 / 64, B_SZ / 128), 256>>>(
        h1, W1b, b1b, nullptr, h2, B_SZ, 512, 128);
    // L1c: [8192,512] @ [512,128]   BM=64
    tgemm_kernel<64, true, false><<<dim3(128 / 64, B_SZ / 64), 256>>>(
        h2, W1c, b1c, nullptr, h3, B_SZ, 128, 512);
    // L1d: [8192,128] @ [128,64] + knowledge (fused add)  BM=64
    tgemm_kernel<64, true, true><<<dim3(CC / 64, B_SZ / 64), 256>>>(
        h3, W1d, b1d, know, h4, B_SZ, CC, 128);
    // L2:  [8192,64] @ [64,1024]    BM=128 -> grid 16 x 64 = 1024 blocks
    tgemm_kernel<128, false, false><<<dim3(OUT_SZ / 64, B_SZ / 128), 256>>>(
        h4, W2, b2, nullptr, out, B_SZ, OUT_SZ, CC);
}

// round 9
// speedup vs baseline: 3.2721x; 1.8477x over previous
#include <cuda_runtime.h>
#include <cuda_bf16.h>
#include <cstdint>

// Shapes (fixed per reference)
#define B_SZ     8192
#define K_SZ     50
#define KG_DIM   64
#define IN_SZ    512
#define CC       64
#define OUT_SZ   1024

// ---------------------------------------------------------------------------
// Scratch (static device globals -- no runtime allocation allowed)
// ---------------------------------------------------------------------------
__device__ float g_h1[B_SZ * 128];
__device__ float g_h2[B_SZ * 512];
__device__ float g_h3[B_SZ * 128];
__device__ float g_h4[B_SZ * CC];
__device__ float g_know[B_SZ * CC];
__device__ int   g_cnt[B_SZ];
__device__ int   g_cidx[B_SZ * K_SZ];

// ---------------------------------------------------------------------------
// tf32 helpers
// ---------------------------------------------------------------------------
__device__ __forceinline__ float to_tf32(float x) {
    uint32_t u;
    asm("cvt.rna.tf32.f32 %0, %1;" : "=r"(u) : "f"(x));
    return __uint_as_float(u);
}
__device__ __forceinline__ void mma_tf32(float* d, const uint32_t* a, const uint32_t* b) {
    asm volatile(
        "mma.sync.aligned.m16n8k8.row.col.f32.tf32.tf32.f32 "
        "{%0,%1,%2,%3}, {%4,%5,%6,%7}, {%8,%9}, {%0,%1,%2,%3};"
        : "+f"(d[0]), "+f"(d[1]), "+f"(d[2]), "+f"(d[3])
        : "r"(a[0]), "r"(a[1]), "r"(a[2]), "r"(a[3]), "r"(b[0]), "r"(b[1]));
}

// ---------------------------------------------------------------------------
// Kernel 1: warp-per-row compaction of masked gather indices.
// ---------------------------------------------------------------------------
__global__ void __launch_bounds__(256) compact_kernel(
    const int* __restrict__ idx, const int* __restrict__ mask,
    int* __restrict__ cidx, int* __restrict__ cnt)
{
    int b = blockIdx.x * (blockDim.x >> 5) + (threadIdx.x >> 5);
    if (b >= B_SZ) return;
    int l = threadIdx.x & 31;
    int base = b * K_SZ;
    int c = 0;
    #pragma unroll
    for (int k0 = 0; k0 < K_SZ; k0 += 32) {
        int k = k0 + l;
        bool m = (k < K_SZ) && (mask[base + k] != 0);
        unsigned bal = __ballot_sync(0xffffffffu, m);
        int pos = c + __popc(bal & ((1u << l) - 1u));
        if (m) cidx[base + pos] = idx[base + k];
        c += __popc(bal);
    }
    if (l == 0) cnt[b] = c;
}

// ---------------------------------------------------------------------------
// Kernel 2: knowledge branch via tf32 tensor cores.
//   knowledge[b][c] = sum_j relu( kg[cidx[b][j]] . Wkg[:,c] + bkg[c] )
// 128 threads = 4 warps, one warp per batch. Wkg staged once/block in smem
// ([k][n], tf32, LD=68 -> conflict-free B frags). Each warp gathers its
// batch's compacted rows in 16-row chunks into a private smem slot
// ([r][k], tf32, LD=68 -> conflict-free A frags), runs m16n8k8 mma over
// all 64 output cols (8 n8-tiles x 8 k8-steps), then applies bias+ReLU and
// accumulates ONLY valid rows (mask r<nr) into per-thread column sums.
// Final shfl-xor reduction over the g dimension; one float2 store per lane.
// ---------------------------------------------------------------------------
#define KLD 68
__global__ void __launch_bounds__(128) knowledge_mma_kernel(
    const float* __restrict__ kg, const float* __restrict__ Wkg,
    const float* __restrict__ bkg, const int* __restrict__ cidx,
    const int* __restrict__ cnt, float* __restrict__ know)
{
    __shared__ float Ws[KG_DIM * KLD];      // Wkg as [k][n] tf32 (17.4 KB)
    __shared__ float Ag[4][16 * KLD];       // per-warp gathered rows [r][k] (17.4 KB)

    int tid = threadIdx.x;

    // stage Wkg -> tf32 smem (row-major [k][n], padded)
    for (int i = tid * 4; i < KG_DIM * CC; i += 128 * 4) {
        int k = i >> 6, c = i & 63;
        float4 w4 = *(const float4*)&Wkg[i];
        *(float4*)&Ws[k * KLD + c] =
            make_float4(to_tf32(w4.x), to_tf32(w4.y), to_tf32(w4.z), to_tf32(w4.w));
    }
    __syncthreads();

    int w  = tid >> 5;
    int l  = tid & 31;
    int g  = l >> 2;          // groupID 0..7
    int tg = l & 3;           // thread-in-group 0..3
    int b  = blockIdx.x * 4 + w;

    // bias for this thread's output cols: col = n8*8 + 2tg (+1)
    float bf[8][2];
    #pragma unroll
    for (int n8 = 0; n8 < 8; n8++) {
        float2 t = *(const float2*)&bkg[n8 * 8 + 2 * tg];
        bf[n8][0] = t.x; bf[n8][1] = t.y;
    }

    int n = cnt[b];
    const int* cp = cidx + b * K_SZ;

    float cs[8][2];
    #pragma unroll
    for (int n8 = 0; n8 < 8; n8++) { cs[n8][0] = 0.f; cs[n8][1] = 0.f; }

    for (int c0 = 0; c0 < n; c0 += 16) {
        int nr = min(16, n - c0);
        // gather chunk rows (tf32) into this warp's slot
        for (int r = 0; r < nr; r++) {
            int row = cp[c0 + r];
            float2 g2 = *(const float2*)(kg + (long)row * KG_DIM + 2 * l);
            *(float2*)&Ag[w][r * KLD + 2 * l] = make_float2(to_tf32(g2.x), to_tf32(g2.y));
        }
        __syncwarp();

        float acc[8][4];
        #pragma unroll
        for (int n8 = 0; n8 < 8; n8++)
            #pragma unroll
            for (int r = 0; r < 4; r++) acc[n8][r] = 0.f;

        #pragma unroll
        for (int ks = 0; ks < KG_DIM; ks += 8) {
            uint32_t af[4];
            const float* ap = &Ag[w][g * KLD + ks + tg];
            af[0] = __float_as_uint(ap[0]);            // (g,    k+tg)
            af[1] = __float_as_uint(ap[8 * KLD]);      // (g+8,  k+tg)
            af[2] = __float_as_uint(ap[4]);            // (g,    k+tg+4)
            af[3] = __float_as_uint(ap[8 * KLD + 4]);  // (g+8,  k+tg+4)
            #pragma unroll
            for (int n8 = 0; n8 < 8; n8++) {
                uint32_t bfr[2];
                const float* bp = &Ws[(ks + tg) * KLD + n8 * 8 + g];
                bfr[0] = __float_as_uint(bp[0]);           // (k+tg,   n+g)
                bfr[1] = __float_as_uint(bp[4 * KLD]);     // (k+tg+4, n+g)
                mma_tf32(acc[n8], af, bfr);
            }
        }

        // bias + relu + masked row accumulation (rows g and g+8 of this chunk)
        bool v0 = (g     < nr);
        bool v1 = (g + 8 < nr);
        #pragma unroll
        for (int n8 = 0; n8 < 8; n8++) {
            if (v0) {
                cs[n8][0] += fmaxf(acc[n8][0] + bf[n8][0], 0.f);
                cs[n8][1] += fmaxf(acc[n8][1] + bf[n8][1], 0.f);
            }
            if (v1) {
                cs[n8][0] += fmaxf(acc[n8][2] + bf[n8][0], 0.f);
                cs[n8][1] += fmaxf(acc[n8][3] + bf[n8][1], 0.f);
            }
        }
        __syncwarp();   // protect Ag before next gather
    }

    // reduce column sums across the g dimension (lane bits 2..4)
    #pragma unroll
    for (int n8 = 0; n8 < 8; n8++)
        #pragma unroll
        for (int j = 0; j < 2; j++) {
            float v = cs[n8][j];
            v += __shfl_xor_sync(0xffffffffu, v, 4);
            v += __shfl_xor_sync(0xffffffffu, v, 8);
            v += __shfl_xor_sync(0xffffffffu, v, 16);
            cs[n8][j] = v;
        }

    // lane (g,tg) writes cols g*8 + 2tg, +1 (select cs[g] without dynamic idx)
    float o0 = 0.f, o1 = 0.f;
    #pragma unroll
    for (int n8 = 0; n8 < 8; n8++)
        if (n8 == g) { o0 = cs[n8][0]; o1 = cs[n8][1]; }
    *(float2*)&know[(long)b * CC + g * 8 + 2 * tg] = make_float2(o0, o1);
}

// ---------------------------------------------------------------------------
// Kernel 3: tf32 tensor-core GEMM  C = act(A @ W + bias) [+ addk]
// A:[M,K] row-major, W:[K,N] row-major, C:[M,N]. 256 threads = 8 warps
// arranged 4(m) x 2(n). BN=64; BK templated (16 or 32).
// Inputs rounded to tf32 at smem staging; fp32 accum; exact-fp32 epilogue.
// Double-buffered smem with register prefetch. Exact tile multiples only.
// ---------------------------------------------------------------------------
template <int BM_, int BK_, bool RELU, bool ADDK>
__global__ void __launch_bounds__(256) tgemm_kernel(
    const float* __restrict__ A, const float* __restrict__ W,
    const float* __restrict__ bias, const float* __restrict__ addk,
    float* __restrict__ C, int M, int N, int K)
{
    constexpr int BN_ = 64;
    constexpr int ALD = BK_ + 4;   // mod-32 == 4 or 20 -> conflict-free frags
    constexpr int BLD = BN_ + 4;
    constexpr int MT  = BM_ / 64;  // m16-tiles per warp (2 or 1)
    constexpr int A_PT = (BM_ * BK_ / 4) / 256;
    constexpr int B_PT = (BK_ * BN_ / 4) / 256;
    constexpr int ACOLS4 = BK_ / 4;

    __shared__ float As[2][BM_ * ALD];   // As[m][k]
    __shared__ float Bs[2][BK_ * BLD];   // Bs[k][n]

    int tid = threadIdx.x;
    int m0 = blockIdx.y * BM_;
    int n0 = blockIdx.x * BN_;

    // global->smem load mappings
    int a_row[A_PT], a_col[A_PT];
    const float* Ap[A_PT];
    #pragma unroll
    for (int t = 0; t < A_PT; t++) {
        int id = tid + t * 256;
        a_row[t] = id / ACOLS4;
        a_col[t] = (id % ACOLS4) * 4;
        Ap[t] = A + (long)(m0 + a_row[t]) * K + a_col[t];
    }
    int b_row[B_PT], b_col[B_PT];
    const float* Bp[B_PT];
    #pragma unroll
    for (int t = 0; t < B_PT; t++) {
        int id = tid + t * 256;
        b_row[t] = id >> 4;
        b_col[t] = (id & 15) * 4;
        Bp[t] = W + (long)b_row[t] * N + n0 + b_col[t];
    }

    // warp / fragment coordinates
    int wid = tid >> 5;
    int lane = tid & 31;
    int g  = lane >> 2;
    int tg = lane & 3;
    int wm = wid & 3;
    int wn = wid >> 2;
    int wmb = wm * (BM_ / 4);
    int wnb = wn * 32;

    float acc[MT][4][4];
    #pragma unroll
    for (int mt = 0; mt < MT; mt++)
        #pragma unroll
        for (int nt = 0; nt < 4; nt++)
            #pragma unroll
            for (int r = 0; r < 4; r++) acc[mt][nt][r] = 0.f;

    float4 pa[A_PT], pb[B_PT];

    // preload chunk 0
    #pragma unroll
    for (int t = 0; t < A_PT; t++) { pa[t] = *(const float4*)Ap[t]; Ap[t] += BK_; }
    #pragma unroll
    for (int t = 0; t < B_PT; t++) { pb[t] = *(const float4*)Bp[t]; Bp[t] += (long)BK_ * N; }
    #pragma unroll
    for (int t = 0; t < A_PT; t++)
        *(float4*)&As[0][a_row[t] * ALD + a_col[t]] =
            make_float4(to_tf32(pa[t].x), to_tf32(pa[t].y), to_tf32(pa[t].z), to_tf32(pa[t].w));
    #pragma unroll
    for (int t = 0; t < B_PT; t++)
        *(float4*)&Bs[0][b_row[t] * BLD + b_col[t]] =
            make_float4(to_tf32(pb[t].x), to_tf32(pb[t].y), to_tf32(pb[t].z), to_tf32(pb[t].w));
    __syncthreads();

    int nchunks = K / BK_;
    for (int kt = 0; kt < nchunks; kt++) {
        int cur = kt & 1;
        bool more = (kt + 1 < nchunks);
        if (more) {
            #pragma unroll
            for (int t = 0; t < A_PT; t++) { pa[t] = *(const float4*)Ap[t]; Ap[t] += BK_; }
            #pragma unroll
            for (int t = 0; t < B_PT; t++) { pb[t] = *(const float4*)Bp[t]; Bp[t] += (long)BK_ * N; }
        }

        const float* Asc = As[cur];
        const float* Bsc = Bs[cur];
        #pragma unroll
        for (int ks = 0; ks < BK_; ks += 8) {
            uint32_t af[MT][4];
            #pragma unroll
            for (int mt = 0; mt < MT; mt++) {
                const float* ap = &Asc[(wmb + mt * 16 + g) * ALD + ks + tg];
                af[mt][0] = __float_as_uint(ap[0]);
                af[mt][1] = __float_as_uint(ap[8 * ALD]);
                af[mt][2] = __float_as_uint(ap[4]);
                af[mt][3] = __float_as_uint(ap[8 * ALD + 4]);
            }
            uint32_t bf[4][2];
            #pragma unroll
            for (int nt = 0; nt < 4; nt++) {
                const float* bp = &Bsc[(ks + tg) * BLD + wnb + nt * 8 + g];
                bf[nt][0] = __float_as_uint(bp[0]);
                bf[nt][1] = __float_as_uint(bp[4 * BLD]);
            }
            #pragma unroll
            for (int mt = 0; mt < MT; mt++)
                #pragma unroll
                for (int nt = 0; nt < 4; nt++)
                    mma_tf32(acc[mt][nt], af[mt], bf[nt]);
        }

        if (more) {
            int nxt = cur ^ 1;
            #pragma unroll
            for (int t = 0; t < A_PT; t++)
                *(float4*)&As[nxt][a_row[t] * ALD + a_col[t]] =
                    make_float4(to_tf32(pa[t].x), to_tf32(pa[t].y), to_tf32(pa[t].z), to_tf32(pa[t].w));
            #pragma unroll
            for (int t = 0; t < B_PT; t++)
                *(float4*)&Bs[nxt][b_row[t] * BLD + b_col[t]] =
                    make_float4(to_tf32(pb[t].x), to_tf32(pb[t].y), to_tf32(pb[t].z), to_tf32(pb[t].w));
            __syncthreads();
        }
    }

    // epilogue (exact fp32)
    #pragma unroll
    for (int nt = 0; nt < 4; nt++) {
        int col = n0 + wnb + nt * 8 + tg * 2;
        float2 bs2 = *(const float2*)&bias[col];
        #pragma unroll
        for (int mt = 0; mt < MT; mt++) {
            int r0 = m0 + wmb + mt * 16 + g;
            int r1 = r0 + 8;
            float v00 = acc[mt][nt][0] + bs2.x;
            float v01 = acc[mt][nt][1] + bs2.y;
            float v10 = acc[mt][nt][2] + bs2.x;
            float v11 = acc[mt][nt][3] + bs2.y;
            if (RELU) {
                v00 = fmaxf(v00, 0.f); v01 = fmaxf(v01, 0.f);
                v10 = fmaxf(v10, 0.f); v11 = fmaxf(v11, 0.f);
            }
            if (ADDK) {
                float2 k0 = *(const float2*)&addk[(long)r0 * N + col];
                float2 k1 = *(const float2*)&addk[(long)r1 * N + col];
                v00 += k0.x; v01 += k0.y; v10 += k1.x; v11 += k1.y;
            }
            *(float2*)&C[(long)r0 * N + col] = make_float2(v00, v01);
            *(float2*)&C[(long)r1 * N + col] = make_float2(v10, v11);
        }
    }
}

// ---------------------------------------------------------------------------
// Launcher
// Input order (metadata): x, kg, idx, mask, Wkg, bkg, W1a,b1a, W1b,b1b,
//                         W1c,b1c, W1d,b1d, W2,b2.  Output: float [8192,1024].
// ---------------------------------------------------------------------------
extern "C" void kernel_launch(void* const* d_in, const int* in_sizes, int n_in,
                              void* d_out, int out_size)
{
    const float* x    = (const float*)d_in[0];
    const float* kg   = (const float*)d_in[1];
    const int*   idx  = (const int*)  d_in[2];
    const int*   mask = (const int*)  d_in[3];
    const float* Wkg  = (const float*)d_in[4];
    const float* bkg  = (const float*)d_in[5];
    const float* W1a  = (const float*)d_in[6];
    const float* b1a  = (const float*)d_in[7];
    const float* W1b  = (const float*)d_in[8];
    const float* b1b  = (const float*)d_in[9];
    const float* W1c  = (const float*)d_in[10];
    const float* b1c  = (const float*)d_in[11];
    const float* W1d  = (const float*)d_in[12];
    const float* b1d  = (const float*)d_in[13];
    const float* W2   = (const float*)d_in[14];
    const float* b2   = (const float*)d_in[15];
    float* out = (float*)d_out;

    float *h1, *h2, *h3, *h4, *know;
    int *cnt, *cidx;
    cudaGetSymbolAddress((void**)&h1,   g_h1);
    cudaGetSymbolAddress((void**)&h2,   g_h2);
    cudaGetSymbolAddress((void**)&h3,   g_h3);
    cudaGetSymbolAddress((void**)&h4,   g_h4);
    cudaGetSymbolAddress((void**)&know, g_know);
    cudaGetSymbolAddress((void**)&cnt,  g_cnt);
    cudaGetSymbolAddress((void**)&cidx, g_cidx);

    // knowledge branch (tf32 tensor cores)
    compact_kernel<<<B_SZ / 8, 256>>>(idx, mask, cidx, cnt);
    knowledge_mma_kernel<<<B_SZ / 4, 128>>>(kg, Wkg, bkg, cidx, cnt, know);

    // dense MLP chain (tf32 tensor cores, fp32 accumulate)
    // L1a: [8192,512] @ [512,128]   BM=64, BK=32 -> 256 blocks, 16 chunks
    tgemm_kernel<64, 32, true, false><<<dim3(128 / 64, B_SZ / 64), 256>>>(
        x,  W1a, b1a, nullptr, h1, B_SZ, 128, IN_SZ);
    // L1b: [8192,128] @ [128,512]   BM=128, BK=16 -> 512 blocks
    tgemm_kernel<128, 16, true, false><<<dim3(512 / 64, B_SZ / 128), 256>>>(
        h1, W1b, b1b, nullptr, h2, B_SZ, 512, 128);
    // L1c: [8192,512] @ [512,128]   BM=64, BK=32
    tgemm_kernel<64, 32, true, false><<<dim3(128 / 64, B_SZ / 64), 256>>>(
        h2, W1c, b1c, nullptr, h3, B_SZ, 128, 512);
    // L1d: [8192,128] @ [128,64] + knowledge (fused add)  BM=64, BK=32
    tgemm_kernel<64, 32, true, true><<<dim3(CC / 64, B_SZ / 64), 256>>>(
        h3, W1d, b1d, know, h4, B_SZ, CC, 128);
    // L2:  [8192,64] @ [64,1024]    BM=128, BK=16 -> 1024 blocks
    tgemm_kernel<128, 16, false, false><<<dim3(OUT_SZ / 64, B_SZ / 128), 256>>>(
        h4, W2, b2, nullptr, out, B_SZ, OUT_SZ, CC);
}

// round 10
// speedup vs baseline: 3.5641x; 1.0892x over previous
#include <cuda_runtime.h>
#include <cuda_bf16.h>
#include <cstdint>

// Shapes (fixed per reference)
#define B_SZ     8192
#define K_SZ     50
#define KG_DIM   64
#define IN_SZ    512
#define CC       64
#define OUT_SZ   1024

// ---------------------------------------------------------------------------
// Scratch (static device globals -- no runtime allocation allowed)
// ---------------------------------------------------------------------------
__device__ __align__(16) float g_h1[B_SZ * 128];
__device__ __align__(16) float g_h2[B_SZ * 512];
__device__ __align__(16) float g_h3[B_SZ * 128];
__device__ __align__(16) float g_h4[B_SZ * CC];
__device__ __align__(16) float g_know[B_SZ * CC];
__device__ __align__(16) float g_xt[B_SZ * IN_SZ];   // tf32-rounded x
__device__ __align__(16) float g_wt[270336];         // tf32-rounded weights (packed)
__device__ int   g_cnt[B_SZ];
__device__ int   g_cidx[B_SZ * K_SZ];

// packed weight offsets (floats)
#define W1A_OFF 0
#define W1B_OFF 65536
#define W1C_OFF 131072
#define W1D_OFF 196608
#define W2_OFF  204800

// ---------------------------------------------------------------------------
// tf32 / mma / cp.async helpers
// ---------------------------------------------------------------------------
__device__ __forceinline__ float to_tf32(float x) {
    uint32_t u;
    asm("cvt.rna.tf32.f32 %0, %1;" : "=r"(u) : "f"(x));
    return __uint_as_float(u);
}
__device__ __forceinline__ float4 cvt4(float4 v) {
    return make_float4(to_tf32(v.x), to_tf32(v.y), to_tf32(v.z), to_tf32(v.w));
}
__device__ __forceinline__ void mma_tf32(float* d, const uint32_t* a, const uint32_t* b) {
    asm volatile(
        "mma.sync.aligned.m16n8k8.row.col.f32.tf32.tf32.f32 "
        "{%0,%1,%2,%3}, {%4,%5,%6,%7}, {%8,%9}, {%0,%1,%2,%3};"
        : "+f"(d[0]), "+f"(d[1]), "+f"(d[2]), "+f"(d[3])
        : "r"(a[0]), "r"(a[1]), "r"(a[2]), "r"(a[3]), "r"(b[0]), "r"(b[1]));
}
__device__ __forceinline__ void cp16(void* smem_dst, const void* gsrc) {
    unsigned s = (unsigned)__cvta_generic_to_shared(smem_dst);
    asm volatile("cp.async.ca.shared.global [%0], [%1], 16;" :: "r"(s), "l"(gsrc));
}
__device__ __forceinline__ void cp_commit() { asm volatile("cp.async.commit_group;"); }
__device__ __forceinline__ void cp_wait0()  { asm volatile("cp.async.wait_group 0;"); }

// ---------------------------------------------------------------------------
// Kernel 0: preconvert x and all weights to tf32 (rna) once.
// x: 1048576 float4s -> g_xt.  Weights: 67584 float4s -> g_wt (packed).
// ---------------------------------------------------------------------------
__global__ void __launch_bounds__(256) preconvert_kernel(
    const float* __restrict__ x,
    const float* __restrict__ W1a, const float* __restrict__ W1b,
    const float* __restrict__ W1c, const float* __restrict__ W1d,
    const float* __restrict__ W2)
{
    const int XT_F4 = (B_SZ * IN_SZ) / 4;   // 1048576
    int i4 = blockIdx.x * 256 + threadIdx.x;
    if (i4 < XT_F4) {
        ((float4*)g_xt)[i4] = cvt4(((const float4*)x)[i4]);
        return;
    }
    int j = i4 - XT_F4;
    const float* src; int dst;
    if      (j < 16384) { src = W1a; dst = W1A_OFF / 4; }
    else if (j < 32768) { src = W1b; dst = W1B_OFF / 4; j -= 16384; }
    else if (j < 49152) { src = W1c; dst = W1C_OFF / 4; j -= 32768; }
    else if (j < 51200) { src = W1d; dst = W1D_OFF / 4; j -= 49152; }
    else                { src = W2;  dst = W2_OFF  / 4; j -= 51200; }
    ((float4*)g_wt)[dst + j] = cvt4(((const float4*)src)[j]);
}

// ---------------------------------------------------------------------------
// Kernel 1: warp-per-row compaction of masked gather indices.
// ---------------------------------------------------------------------------
__global__ void __launch_bounds__(256) compact_kernel(
    const int* __restrict__ idx, const int* __restrict__ mask,
    int* __restrict__ cidx, int* __restrict__ cnt)
{
    int b = blockIdx.x * (blockDim.x >> 5) + (threadIdx.x >> 5);
    if (b >= B_SZ) return;
    int l = threadIdx.x & 31;
    int base = b * K_SZ;
    int c = 0;
    #pragma unroll
    for (int k0 = 0; k0 < K_SZ; k0 += 32) {
        int k = k0 + l;
        bool m = (k < K_SZ) && (mask[base + k] != 0);
        unsigned bal = __ballot_sync(0xffffffffu, m);
        int pos = c + __popc(bal & ((1u << l) - 1u));
        if (m) cidx[base + pos] = idx[base + k];
        c += __popc(bal);
    }
    if (l == 0) cnt[b] = c;
}

// ---------------------------------------------------------------------------
// GEMM body: tf32 tensor-core GEMM  C = act(A @ W + bias) [+ addk]
// cp.async double-buffered staging (A and W already tf32-valued).
// 256 threads = 8 warps as 4(m) x 2(n); BN=64; frag mapping identical to the
// proven Round-8 kernel. ROUND: store outputs tf32-rounded (pre-rounding for
// the next layer's mma -- mathematically identical to staging-side cvt).
// ---------------------------------------------------------------------------
template <int BM_, int BK_, bool RELU, bool ADDK, bool ROUND>
__device__ __forceinline__ void gemm_body(
    float* smem, int bxn, int bym,
    const float* __restrict__ A, const float* __restrict__ W,
    const float* __restrict__ bias, const float* __restrict__ addk,
    float* __restrict__ C, int M, int N, int K)
{
    constexpr int BN_ = 64;
    constexpr int ALD = BK_ + 4;
    constexpr int BLD = BN_ + 4;
    constexpr int MT  = BM_ / 64;
    constexpr int A_PT = (BM_ * BK_ / 4) / 256;
    constexpr int B_PT = (BK_ * BN_ / 4) / 256;
    constexpr int ACOLS4 = BK_ / 4;
    constexpr int ASZ = BM_ * ALD;
    constexpr int BSZ = BK_ * BLD;

    float* As = smem;              // [2][ASZ]
    float* Bs = smem + 2 * ASZ;    // [2][BSZ]

    int tid = threadIdx.x;
    int m0 = bym * BM_;
    int n0 = bxn * BN_;

    // global->smem load mappings
    int a_off[A_PT];
    const float* Ap[A_PT];
    #pragma unroll
    for (int t = 0; t < A_PT; t++) {
        int id = tid + t * 256;
        int ar = id / ACOLS4, ac = (id % ACOLS4) * 4;
        a_off[t] = ar * ALD + ac;
        Ap[t] = A + (long)(m0 + ar) * K + ac;
    }
    int b_off[B_PT];
    const float* Bp[B_PT];
    #pragma unroll
    for (int t = 0; t < B_PT; t++) {
        int id = tid + t * 256;
        int br = id >> 4, bc = (id & 15) * 4;
        b_off[t] = br * BLD + bc;
        Bp[t] = W + (long)br * N + n0 + bc;
    }

    // warp / fragment coordinates
    int wid = tid >> 5;
    int lane = tid & 31;
    int g  = lane >> 2;
    int tg = lane & 3;
    int wm = wid & 3;
    int wn = wid >> 2;
    int wmb = wm * (BM_ / 4);
    int wnb = wn * 32;

    float acc[MT][4][4];
    #pragma unroll
    for (int mt = 0; mt < MT; mt++)
        #pragma unroll
        for (int nt = 0; nt < 4; nt++)
            #pragma unroll
            for (int r = 0; r < 4; r++) acc[mt][nt][r] = 0.f;

    // preload stage 0
    #pragma unroll
    for (int t = 0; t < A_PT; t++) { cp16(&As[a_off[t]], Ap[t]); Ap[t] += BK_; }
    #pragma unroll
    for (int t = 0; t < B_PT; t++) { cp16(&Bs[b_off[t]], Bp[t]); Bp[t] += (long)BK_ * N; }
    cp_commit();

    int nchunks = K / BK_;
    for (int kt = 0; kt < nchunks; kt++) {
        int cur = kt & 1;
        bool more = (kt + 1 < nchunks);
        cp_wait0();
        __syncthreads();
        if (more) {
            int nxt = cur ^ 1;
            #pragma unroll
            for (int t = 0; t < A_PT; t++) { cp16(&As[nxt * ASZ + a_off[t]], Ap[t]); Ap[t] += BK_; }
            #pragma unroll
            for (int t = 0; t < B_PT; t++) { cp16(&Bs[nxt * BSZ + b_off[t]], Bp[t]); Bp[t] += (long)BK_ * N; }
            cp_commit();
        }

        const float* Asc = As + cur * ASZ;
        const float* Bsc = Bs + cur * BSZ;
        #pragma unroll
        for (int ks = 0; ks < BK_; ks += 8) {
            uint32_t af[MT][4];
            #pragma unroll
            for (int mt = 0; mt < MT; mt++) {
                const float* ap = &Asc[(wmb + mt * 16 + g) * ALD + ks + tg];
                af[mt][0] = __float_as_uint(ap[0]);
                af[mt][1] = __float_as_uint(ap[8 * ALD]);
                af[mt][2] = __float_as_uint(ap[4]);
                af[mt][3] = __float_as_uint(ap[8 * ALD + 4]);
            }
            uint32_t bf[4][2];
            #pragma unroll
            for (int nt = 0; nt < 4; nt++) {
                const float* bp = &Bsc[(ks + tg) * BLD + wnb + nt * 8 + g];
                bf[nt][0] = __float_as_uint(bp[0]);
                bf[nt][1] = __float_as_uint(bp[4 * BLD]);
            }
            #pragma unroll
            for (int mt = 0; mt < MT; mt++)
                #pragma unroll
                for (int nt = 0; nt < 4; nt++)
                    mma_tf32(acc[mt][nt], af[mt], bf[nt]);
        }
        __syncthreads();
    }

    // epilogue (exact fp32; optional tf32 rounding of stored outputs)
    #pragma unroll
    for (int nt = 0; nt < 4; nt++) {
        int col = n0 + wnb + nt * 8 + tg * 2;
        float2 bs2 = *(const float2*)&bias[col];
        #pragma unroll
        for (int mt = 0; mt < MT; mt++) {
            int r0 = m0 + wmb + mt * 16 + g;
            int r1 = r0 + 8;
            float v00 = acc[mt][nt][0] + bs2.x;
            float v01 = acc[mt][nt][1] + bs2.y;
            float v10 = acc[mt][nt][2] + bs2.x;
            float v11 = acc[mt][nt][3] + bs2.y;
            if (RELU) {
                v00 = fmaxf(v00, 0.f); v01 = fmaxf(v01, 0.f);
                v10 = fmaxf(v10, 0.f); v11 = fmaxf(v11, 0.f);
            }
            if (ADDK) {
                float2 k0 = *(const float2*)&addk[(long)r0 * N + col];
                float2 k1 = *(const float2*)&addk[(long)r1 * N + col];
                v00 += k0.x; v01 += k0.y; v10 += k1.x; v11 += k1.y;
            }
            if (ROUND) {
                v00 = to_tf32(v00); v01 = to_tf32(v01);
                v10 = to_tf32(v10); v11 = to_tf32(v11);
            }
            *(float2*)&C[(long)r0 * N + col] = make_float2(v00, v01);
            *(float2*)&C[(long)r1 * N + col] = make_float2(v10, v11);
        }
    }
}

// ---------------------------------------------------------------------------
// Knowledge body (256 threads, 4 warp-PAIRS, one batch per pair).
//   knowledge[b][c] = sum_j relu( kg[cidx[b][j]] . Wkg[:,c] + bkg[c] )
// Wkg staged once/block as tf32 [k][n] (LD=68). Pair (warps 2p,2p+1) shares
// a 16-row gathered-chunk slot: warp h gathers rows r%2==h, then computes
// n8-tiles h*4..h*4+3 (cols h*32..h*32+31). Pair-scoped named barrier
// (bar.sync 1+p, 64) -- no block barrier in the variable-count loop, so
// differing cnt[b] across pairs cannot deadlock. Masked row accumulation,
// warp-local shfl reduction over g, direct stores.
// ---------------------------------------------------------------------------
__device__ __forceinline__ void knowledge_body(
    float* smem, int kb,
    const float* __restrict__ kg, const float* __restrict__ Wkg,
    const float* __restrict__ bkg, const int* __restrict__ cidx,
    const int* __restrict__ cnt, float* __restrict__ know)
{
    float* Ws = smem;              // [64*68] tf32 Wkg [k][n]
    float* Ag = smem + KG_DIM * 68;  // [4][16*68]

    int tid = threadIdx.x;
    for (int i = tid * 4; i < KG_DIM * CC; i += 256 * 4) {
        int k = i >> 6, c = i & 63;
        *(float4*)&Ws[k * 68 + c] = cvt4(*(const float4*)&Wkg[i]);
    }
    __syncthreads();

    int w = tid >> 5, l = tid & 31;
    int pair = w >> 1, h = w & 1;
    int g = l >> 2, tg = l & 3;
    int b = kb * 4 + pair;
    float* Agp = Ag + pair * 16 * 68;
    int barid = 1 + pair;

    // bias for this warp's 4 n8-tiles: col = h*32 + n8*8 + 2tg
    float bf[4][2];
    #pragma unroll
    for (int n8 = 0; n8 < 4; n8++) {
        float2 t = *(const float2*)&bkg[h * 32 + n8 * 8 + 2 * tg];
        bf[n8][0] = t.x; bf[n8][1] = t.y;
    }

    int n = cnt[b];
    const int* cp = cidx + b * K_SZ;

    float cs[4][2];
    #pragma unroll
    for (int n8 = 0; n8 < 4; n8++) { cs[n8][0] = 0.f; cs[n8][1] = 0.f; }

    for (int c0 = 0; c0 < n; c0 += 16) {
        int nr = min(16, n - c0);
        for (int r = h; r < nr; r += 2) {
            int row = cp[c0 + r];
            float2 g2 = *(const float2*)(kg + (long)row * KG_DIM + 2 * l);
            *(float2*)&Agp[r * 68 + 2 * l] = make_float2(to_tf32(g2.x), to_tf32(g2.y));
        }
        asm volatile("bar.sync %0, 64;" :: "r"(barid) : "memory");

        float acc[4][4];
        #pragma unroll
        for (int n8 = 0; n8 < 4; n8++)
            #pragma unroll
            for (int r = 0; r < 4; r++) acc[n8][r] = 0.f;

        #pragma unroll
        for (int ks = 0; ks < KG_DIM; ks += 8) {
            uint32_t af[4];
            const float* ap = &Agp[g * 68 + ks + tg];
            af[0] = __float_as_uint(ap[0]);
            af[1] = __float_as_uint(ap[8 * 68]);
            af[2] = __float_as_uint(ap[4]);
            af[3] = __float_as_uint(ap[8 * 68 + 4]);
            #pragma unroll
            for (int n8 = 0; n8 < 4; n8++) {
                uint32_t bfr[2];
                const float* bp = &Ws[(ks + tg) * 68 + h * 32 + n8 * 8 + g];
                bfr[0] = __float_as_uint(bp[0]);
                bfr[1] = __float_as_uint(bp[4 * 68]);
                mma_tf32(acc[n8], af, bfr);
            }
        }

        bool v0 = (g < nr);
        bool v1 = (g + 8 < nr);
        #pragma unroll
        for (int n8 = 0; n8 < 4; n8++) {
            if (v0) {
                cs[n8][0] += fmaxf(acc[n8][0] + bf[n8][0], 0.f);
                cs[n8][1] += fmaxf(acc[n8][1] + bf[n8][1], 0.f);
            }
            if (v1) {
                cs[n8][0] += fmaxf(acc[n8][2] + bf[n8][0], 0.f);
                cs[n8][1] += fmaxf(acc[n8][3] + bf[n8][1], 0.f);
            }
        }
        asm volatile("bar.sync %0, 64;" :: "r"(barid) : "memory");
    }

    // reduce over g (lane bits 2..4); all g-lanes end with the (n8, tg) totals
    #pragma unroll
    for (int n8 = 0; n8 < 4; n8++)
        #pragma unroll
        for (int j = 0; j < 2; j++) {
            float v = cs[n8][j];
            v += __shfl_xor_sync(0xffffffffu, v, 4);
            v += __shfl_xor_sync(0xffffffffu, v, 8);
            v += __shfl_xor_sync(0xffffffffu, v, 16);
            cs[n8][j] = v;
        }

    if (g < 4) {   // lane (g,tg) writes tile g of this warp's half
        float o0 = 0.f, o1 = 0.f;
        #pragma unroll
        for (int n8 = 0; n8 < 4; n8++)
            if (n8 == g) { o0 = cs[n8][0]; o1 = cs[n8][1]; }
        *(float2*)&know[(long)b * CC + h * 32 + g * 8 + 2 * tg] = make_float2(o0, o1);
    }
}

// ---------------------------------------------------------------------------
// Fused kernel: L1a GEMM blocks (0..255) + knowledge blocks (256..2303).
// Union static smem: max(gemm 8960, knowledge 8704) floats = 35.8 KB.
// ---------------------------------------------------------------------------
#define L1A_BLOCKS 256
__global__ void __launch_bounds__(256) fused_l1a_know_kernel(
    const float* __restrict__ xt, const float* __restrict__ w1a,
    const float* __restrict__ b1a, float* __restrict__ h1,
    const float* __restrict__ kg, const float* __restrict__ Wkg,
    const float* __restrict__ bkg, const int* __restrict__ cidx,
    const int* __restrict__ cnt, float* __restrict__ know)
{
    __shared__ __align__(16) float smem[8960];
    if (blockIdx.x < L1A_BLOCKS) {
        gemm_body<64, 32, true, false, true>(
            smem, blockIdx.x & 1, blockIdx.x >> 1,
            xt, w1a, b1a, nullptr, h1, B_SZ, 128, IN_SZ);
    } else {
        knowledge_body(smem, blockIdx.x - L1A_BLOCKS, kg, Wkg, bkg, cidx, cnt, know);
    }
}

// ---------------------------------------------------------------------------
// Standalone GEMM kernel wrapper
// ---------------------------------------------------------------------------
template <int BM_, int BK_, bool RELU, bool ADDK, bool ROUND>
__global__ void __launch_bounds__(256) tgemm2_kernel(
    const float* __restrict__ A, const float* __restrict__ W,
    const float* __restrict__ bias, const float* __restrict__ addk,
    float* __restrict__ C, int M, int N, int K)
{
    constexpr int SM_FLOATS = 2 * BM_ * (BK_ + 4) + 2 * BK_ * 68;
    __shared__ __align__(16) float smem[SM_FLOATS];
    gemm_body<BM_, BK_, RELU, ADDK, ROUND>(
        smem, blockIdx.x, blockIdx.y, A, W, bias, addk, C, M, N, K);
}

// ---------------------------------------------------------------------------
// Launcher
// Input order (metadata): x, kg, idx, mask, Wkg, bkg, W1a,b1a, W1b,b1b,
//                         W1c,b1c, W1d,b1d, W2,b2.  Output: float [8192,1024].
// ---------------------------------------------------------------------------
extern "C" void kernel_launch(void* const* d_in, const int* in_sizes, int n_in,
                              void* d_out, int out_size)
{
    const float* x    = (const float*)d_in[0];
    const float* kg   = (const float*)d_in[1];
    const int*   idx  = (const int*)  d_in[2];
    const int*   mask = (const int*)  d_in[3];
    const float* Wkg  = (const float*)d_in[4];
    const float* bkg  = (const float*)d_in[5];
    const float* W1a  = (const float*)d_in[6];
    const float* b1a  = (const float*)d_in[7];
    const float* W1b  = (const float*)d_in[8];
    const float* b1b  = (const float*)d_in[9];
    const float* W1c  = (const float*)d_in[10];
    const float* b1c  = (const float*)d_in[11];
    const float* W1d  = (const float*)d_in[12];
    const float* b1d  = (const float*)d_in[13];
    const float* W2   = (const float*)d_in[14];
    const float* b2   = (const float*)d_in[15];
    float* out = (float*)d_out;

    float *h1, *h2, *h3, *h4, *know, *xt, *wt;
    int *cnt, *cidx;
    cudaGetSymbolAddress((void**)&h1,   g_h1);
    cudaGetSymbolAddress((void**)&h2,   g_h2);
    cudaGetSymbolAddress((void**)&h3,   g_h3);
    cudaGetSymbolAddress((void**)&h4,   g_h4);
    cudaGetSymbolAddress((void**)&know, g_know);
    cudaGetSymbolAddress((void**)&xt,   g_xt);
    cudaGetSymbolAddress((void**)&wt,   g_wt);
    cudaGetSymbolAddress((void**)&cnt,  g_cnt);
    cudaGetSymbolAddress((void**)&cidx, g_cidx);

    // 0) round x + weights to tf32 once   (1116160 float4s / 256 = 4360 blocks)
    preconvert_kernel<<<4360, 256>>>(x, W1a, W1b, W1c, W1d, W2);
    // 1) mask compaction
    compact_kernel<<<B_SZ / 8, 256>>>(idx, mask, cidx, cnt);
    // 2) fused: L1a GEMM (256 blocks) || knowledge branch (2048 blocks)
    fused_l1a_know_kernel<<<L1A_BLOCKS + B_SZ / 4, 256>>>(
        xt, wt + W1A_OFF, b1a, h1, kg, Wkg, bkg, cidx, cnt, know);
    // 3) L1b: [8192,128] @ [128,512]
    tgemm2_kernel<128, 16, true, false, true><<<dim3(512 / 64, B_SZ / 128), 256>>>(
        h1, wt + W1B_OFF, b1b, nullptr, h2, B_SZ, 512, 128);
    // 4) L1c: [8192,512] @ [512,128]
    tgemm2_kernel<64, 32, true, false, true><<<dim3(128 / 64, B_SZ / 64), 256>>>(
        h2, wt + W1C_OFF, b1c, nullptr, h3, B_SZ, 128, 512);
    // 5) L1d: [8192,128] @ [128,64] + knowledge (fused add)
    tgemm2_kernel<64, 32, true, true, true><<<dim3(CC / 64, B_SZ / 64), 256>>>(
        h3, wt + W1D_OFF, b1d, know, h4, B_SZ, CC, 128);
    // 6) L2: [8192,64] @ [64,1024]  (exact fp32 output)
    tgemm2_kernel<128, 16, false, false, false><<<dim3(OUT_SZ / 64, B_SZ / 128), 256>>>(
        h4, wt + W2_OFF, b2, nullptr, out, B_SZ, OUT_SZ, CC);
}